// round 16
// baseline (speedup 1.0000x reference)
#include <cuda_runtime.h>
#include <cuda_bf16.h>
#include <cstdint>

#define NPTS 8192
#define DIM  512
#define MARGINF 0.3f

#define BM 128
#define BN 128
#define BK 64                    // bf16 elems per K chunk (128 B per row)
#define NCHUNK (DIM/BK)          // 8
#define GB (NPTS/BM)             // 64
#define NPART (GB*(GB+1)/2)      // 2080 upper-triangular tiles

#define STAGES 3
#define STAGE_BYTES 32768        // 16KB A + 16KB B
#define SMEM_BYTES (1024 + STAGES*STAGE_BYTES)

// ---------------- device scratch (no allocations allowed) ----------------
__device__ __nv_bfloat16 g_X[NPTS*DIM];   // 8 MB bf16 copy of inputs
__device__ int   g_lab[NPTS];
__device__ float g_part[NPART];

// ---------------- helpers ----------------
__device__ __forceinline__ uint32_t smem_u32(const void* p){
    uint32_t a;
    asm("{ .reg .u64 t; cvta.to.shared.u64 t, %1; cvt.u32.u64 %0, t; }"
        : "=r"(a) : "l"(p));
    return a;
}
#define SW128(o) ((o) ^ (((o) >> 3) & 0x70))

__device__ __forceinline__ void cp16(uint32_t s, const void* g){
    asm volatile("cp.async.cg.shared.global [%0], [%1], 16;" :: "r"(s), "l"(g));
}
#define CP_COMMIT() asm volatile("cp.async.commit_group;" ::: "memory")
#define CP_WAIT(n)  asm volatile("cp.async.wait_group %0;" :: "n"(n) : "memory")

__device__ __forceinline__ void ldm_x4(uint32_t* r, uint32_t addr){
    asm volatile("ldmatrix.sync.aligned.m8n8.x4.shared.b16 {%0,%1,%2,%3}, [%4];"
                 : "=r"(r[0]), "=r"(r[1]), "=r"(r[2]), "=r"(r[3]) : "r"(addr));
}
__device__ __forceinline__ void mma16816(float* d, const uint32_t* a,
                                         uint32_t b0, uint32_t b1){
    asm volatile(
        "mma.sync.aligned.m16n8k16.row.col.f32.bf16.bf16.f32 "
        "{%0,%1,%2,%3}, {%4,%5,%6,%7}, {%8,%9}, {%0,%1,%2,%3};"
        : "+f"(d[0]), "+f"(d[1]), "+f"(d[2]), "+f"(d[3])
        : "r"(a[0]), "r"(a[1]), "r"(a[2]), "r"(a[3]), "r"(b0), "r"(b1));
}

// ---------------- kernel 1: convert inputs to bf16 + normalize labels ----------------
__global__ void prep_kernel(const float* __restrict__ x, const void* __restrict__ tgt){
    const int idx = blockIdx.x * blockDim.x + threadIdx.x;   // NPTS*DIM/4 threads
    const float4 v = ((const float4*)x)[idx];
    __nv_bfloat162 p0 = __float22bfloat162_rn(make_float2(v.x, v.y));
    __nv_bfloat162 p1 = __float22bfloat162_rn(make_float2(v.z, v.w));
    uint2 st;
    st.x = *(uint32_t*)&p0;
    st.y = *(uint32_t*)&p1;
    ((uint2*)g_X)[idx] = st;

    if (blockIdx.x == 0){
        // detect int64 vs int32 labels: values in [0,128); if int64, all odd words are 0
        const int* w = (const int*)tgt;
        bool is64 = true;
        #pragma unroll 1
        for (int k = 0; k < 64; k++)
            if (w[2*k + 1] != 0) { is64 = false; break; }
        if (is64){
            const long long* t64 = (const long long*)tgt;
            for (int i = threadIdx.x; i < NPTS; i += blockDim.x)
                g_lab[i] = (int)t64[i];
        } else {
            for (int i = threadIdx.x; i < NPTS; i += blockDim.x)
                g_lab[i] = w[i];
        }
    }
}

// ---------------- kernel 2: bf16 HMMA GEMM (single barrier/chunk) ----------------
__global__ void __launch_bounds__(256, 2) contrastive_gemm(){
    extern __shared__ char smem[];
    const uint32_t sb = smem_u32(smem);
    const int tid = threadIdx.x;
    const int wid = tid >> 5, lane = tid & 31;

    // map blockIdx.x -> upper-triangular (bi, bj), bi <= bj
    int bi = 0, rem = blockIdx.x;
    while (rem >= GB - bi){ rem -= GB - bi; bi++; }
    const int bj = bi + rem;
    const int i0 = bi * BM, j0 = bj * BN;
    const bool diag = (bi == bj);

    // labels into smem: ilab[128] @0, jlab[128] @512
    int* ilab = (int*)smem;
    int* jlab = (int*)(smem + 512);
    if (tid < 128) ilab[tid] = g_lab[i0 + tid];
    else           jlab[tid - 128] = g_lab[j0 + (tid - 128)];

    // cp.async loader: 256 threads, 8 threads x 16B per 128B row, 32 rows/pass
    // Diagonal tiles: B content == A content, so skip the B loads entirely and
    // point the B smem region at A below.
    const int rr = tid >> 3, vv = tid & 7;
    auto load_stage = [&](int c){
        const uint32_t sA = sb + 1024 + (c % STAGES) * STAGE_BYTES;
        const uint32_t sB = sA + 16384;
        const int kc = c * BK;
        #pragma unroll
        for (int p = 0; p < 4; p++){
            const int r = rr + p * 32;
            cp16(sA + SW128(r * 128 + vv * 16),
                 g_X + (size_t)(i0 + r) * DIM + kc + vv * 8);
            if (!diag)
                cp16(sB + SW128(r * 128 + vv * 16),
                     g_X + (size_t)(j0 + r) * DIM + kc + vv * 8);
        }
    };

    load_stage(0); CP_COMMIT();
    load_stage(1); CP_COMMIT();

    const int wm0 = (wid & 3) * 32;     // 4 warps in M
    const int wn0 = (wid >> 2) * 64;    // 2 warps in N

    // Dead warps on diagonal tiles: warp region rows [wm0, wm0+32) x cols [0, 64)
    // with wm0 >= 64 is strictly below the diagonal -> every weight is 0.
    // Skip all tensor work; accumulators stay 0 and contribute nothing.
    const bool dead = diag && (wn0 == 0) && (wm0 >= 64);
    const uint32_t boff = diag ? 0u : 16384u;   // B reads alias A region on diag tiles

    float acc[2][8][4];                 // warp tile 32x64
    #pragma unroll
    for (int tm = 0; tm < 2; tm++)
        #pragma unroll
        for (int tn = 0; tn < 8; tn++)
            #pragma unroll
            for (int e = 0; e < 4; e++) acc[tm][tn][e] = 0.f;

    const int lrow = lane & 15, lhi = lane >> 4;

    for (int c = 0; c < NCHUNK; c++){
        CP_WAIT(1);
        __syncthreads();                 // single barrier per chunk (3-stage proof)
        if (c + 2 < NCHUNK) load_stage(c + 2);
        CP_COMMIT();                     // empty commits keep wait_group(1) aligned

        if (!dead){
            const uint32_t sA = sb + 1024 + (c % STAGES) * STAGE_BYTES;
            const uint32_t sB = sA + boff;
            #pragma unroll
            for (int ks = 0; ks < 4; ks++){
                const int cb = ks * 32 + lhi * 16;
                uint32_t a[2][4];
                #pragma unroll
                for (int tm = 0; tm < 2; tm++)
                    ldm_x4(a[tm], sA + SW128((wm0 + tm * 16 + lrow) * 128 + cb));
                uint32_t b[4][4];
                #pragma unroll
                for (int tp = 0; tp < 4; tp++)
                    ldm_x4(b[tp], sB + SW128((wn0 + tp * 16 + lrow) * 128 + cb));
                #pragma unroll
                for (int tm = 0; tm < 2; tm++)
                    #pragma unroll
                    for (int tp = 0; tp < 4; tp++){
                        mma16816(acc[tm][2*tp],     a[tm], b[tp][0], b[tp][2]);
                        mma16816(acc[tm][2*tp + 1], a[tm], b[tp][1], b[tp][3]);
                    }
            }
        }
    }

    // ---------------- fused masked loss on register accumulators ----------------
    const int r0 = lane >> 2, c0 = (lane & 3) * 2;
    float loss = 0.f;
    #pragma unroll
    for (int tm = 0; tm < 2; tm++){
        const int rowA = wm0 + tm * 16 + r0;
        const int liA  = ilab[rowA];
        const int liB  = ilab[rowA + 8];
        #pragma unroll
        for (int tn = 0; tn < 8; tn++){
            const int colb = wn0 + tn * 8 + c0;
            const int lj0 = jlab[colb], lj1 = jlab[colb + 1];
            #pragma unroll
            for (int e = 0; e < 4; e++){
                const float v = acc[tm][tn][e];
                const int row = (e >> 1) ? rowA + 8 : rowA;
                const int li  = (e >> 1) ? liB : liA;
                const int lj  = (e & 1) ? lj1 : lj0;
                float w = 2.f;
                if (diag){
                    const int gi = row, gj = colb + (e & 1);
                    w = (gi < gj) ? 2.f : ((gi == gj) ? 1.f : 0.f);
                }
                float l;
                if (li == lj) l = (v < 1.f) ? (1.f - v) : 0.f;
                else          l = (v > MARGINF) ? v : 0.f;
                loss += w * l;
            }
        }
    }

    // block reduction -> per-tile partial (wsum in stage-0 region, idle by now)
    #pragma unroll
    for (int o = 16; o; o >>= 1) loss += __shfl_xor_sync(0xffffffffu, loss, o);
    float* wsum = (float*)(smem + 1024);
    if (lane == 0) wsum[wid] = loss;
    __syncthreads();
    if (tid == 0){
        float s = 0.f;
        #pragma unroll
        for (int w = 0; w < 8; w++) s += wsum[w];
        g_part[blockIdx.x] = s;
    }
}

// ---------------- kernel 3: deterministic final reduction ----------------
__global__ void reduce_kernel(float* __restrict__ out){
    __shared__ float sm[256];
    const int t = threadIdx.x;
    float v[9];
    #pragma unroll
    for (int k = 0; k < 9; k++){
        const int i = t + k * 256;
        v[k] = (i < NPART) ? g_part[i] : 0.f;
    }
    sm[t] = ((v[0] + v[1]) + (v[2] + v[3])) + ((v[4] + v[5]) + (v[6] + v[7])) + v[8];
    __syncthreads();
    for (int s = 128; s > 0; s >>= 1){
        if (t < s) sm[t] += sm[t + s];
        __syncthreads();
    }
    if (t == 0) out[0] = sm[0] / (float)NPTS;
}

// ---------------- launch ----------------
extern "C" void kernel_launch(void* const* d_in, const int* in_sizes, int n_in,
                              void* d_out, int out_size){
    const float* x   = (const float*)d_in[0];
    const void*  tgt = d_in[1];
    float* out = (float*)d_out;

    cudaFuncSetAttribute(contrastive_gemm,
                         cudaFuncAttributeMaxDynamicSharedMemorySize, SMEM_BYTES);

    prep_kernel<<<NPTS*DIM/1024, 256>>>(x, tgt);
    contrastive_gemm<<<NPART, 256, SMEM_BYTES>>>();
    reduce_kernel<<<1, 256>>>(out);
}

// round 17
// speedup vs baseline: 1.1270x; 1.1270x over previous
#include <cuda_runtime.h>
#include <cuda_bf16.h>
#include <cstdint>

#define NPTS 8192
#define DIM  512
#define MARGINF 0.3f

#define BM 128
#define BN 128
#define BK 64                    // bf16 elems per K chunk (128 B per row)
#define NCHUNK (DIM/BK)          // 8
#define GB (NPTS/BM)             // 64
#define NPART (GB*(GB+1)/2)      // 2080 upper-triangular tiles

#define STAGES 3
#define STAGE_BYTES 32768        // 16KB A + 16KB B
#define SMEM_BYTES (1024 + STAGES*STAGE_BYTES)

// ---------------- device scratch (no allocations allowed) ----------------
__device__ __nv_bfloat16 g_X[NPTS*DIM];   // 8 MB bf16 copy of inputs
__device__ int   g_lab[NPTS];
__device__ float g_part[NPART];

// ---------------- helpers ----------------
__device__ __forceinline__ uint32_t smem_u32(const void* p){
    uint32_t a;
    asm("{ .reg .u64 t; cvta.to.shared.u64 t, %1; cvt.u32.u64 %0, t; }"
        : "=r"(a) : "l"(p));
    return a;
}
#define SW128(o) ((o) ^ (((o) >> 3) & 0x70))

__device__ __forceinline__ void cp16(uint32_t s, const void* g){
    asm volatile("cp.async.cg.shared.global [%0], [%1], 16;" :: "r"(s), "l"(g));
}
#define CP_COMMIT() asm volatile("cp.async.commit_group;" ::: "memory")
#define CP_WAIT(n)  asm volatile("cp.async.wait_group %0;" :: "n"(n) : "memory")

__device__ __forceinline__ void ldm_x4(uint32_t* r, uint32_t addr){
    asm volatile("ldmatrix.sync.aligned.m8n8.x4.shared.b16 {%0,%1,%2,%3}, [%4];"
                 : "=r"(r[0]), "=r"(r[1]), "=r"(r[2]), "=r"(r[3]) : "r"(addr));
}
__device__ __forceinline__ void mma16816(float* d, const uint32_t* a,
                                         uint32_t b0, uint32_t b1){
    asm volatile(
        "mma.sync.aligned.m16n8k16.row.col.f32.bf16.bf16.f32 "
        "{%0,%1,%2,%3}, {%4,%5,%6,%7}, {%8,%9}, {%0,%1,%2,%3};"
        : "+f"(d[0]), "+f"(d[1]), "+f"(d[2]), "+f"(d[3])
        : "r"(a[0]), "r"(a[1]), "r"(a[2]), "r"(a[3]), "r"(b0), "r"(b1));
}

// ---------------- kernel 1: convert inputs to bf16 + normalize labels ----------------
// grid 4096 x 256, one float4 load -> one 8B store per thread (best-measured variant)
__global__ void prep_kernel(const float* __restrict__ x, const void* __restrict__ tgt){
    const int idx = blockIdx.x * blockDim.x + threadIdx.x;   // NPTS*DIM/4 threads
    const float4 v = ((const float4*)x)[idx];
    __nv_bfloat162 p0 = __float22bfloat162_rn(make_float2(v.x, v.y));
    __nv_bfloat162 p1 = __float22bfloat162_rn(make_float2(v.z, v.w));
    uint2 st;
    st.x = *(uint32_t*)&p0;
    st.y = *(uint32_t*)&p1;
    ((uint2*)g_X)[idx] = st;

    if (blockIdx.x == 0){
        // detect int64 vs int32 labels: values in [0,128); if int64, all odd words are 0
        const int* w = (const int*)tgt;
        bool is64 = true;
        #pragma unroll 1
        for (int k = 0; k < 64; k++)
            if (w[2*k + 1] != 0) { is64 = false; break; }
        if (is64){
            const long long* t64 = (const long long*)tgt;
            for (int i = threadIdx.x; i < NPTS; i += blockDim.x)
                g_lab[i] = (int)t64[i];
        } else {
            for (int i = threadIdx.x; i < NPTS; i += blockDim.x)
                g_lab[i] = w[i];
        }
    }
}

// ---------------- kernel 2: bf16 HMMA GEMM (single barrier/chunk) ----------------
__global__ void __launch_bounds__(256, 2) contrastive_gemm(){
    extern __shared__ char smem[];
    const uint32_t sb = smem_u32(smem);
    const int tid = threadIdx.x;
    const int wid = tid >> 5, lane = tid & 31;

    // map blockIdx.x -> upper-triangular (bi, bj), bi <= bj
    int bi = 0, rem = blockIdx.x;
    while (rem >= GB - bi){ rem -= GB - bi; bi++; }
    const int bj = bi + rem;
    const int i0 = bi * BM, j0 = bj * BN;
    const bool diag = (bi == bj);

    // labels into smem: ilab[128] @0, jlab[128] @512
    int* ilab = (int*)smem;
    int* jlab = (int*)(smem + 512);
    if (tid < 128) ilab[tid] = g_lab[i0 + tid];
    else           jlab[tid - 128] = g_lab[j0 + (tid - 128)];

    // cp.async loader: 256 threads, 8 threads x 16B per 128B row, 32 rows/pass
    const int rr = tid >> 3, vv = tid & 7;
    auto load_stage = [&](int c){
        const uint32_t sA = sb + 1024 + (c % STAGES) * STAGE_BYTES;
        const uint32_t sB = sA + 16384;
        const int kc = c * BK;
        #pragma unroll
        for (int p = 0; p < 4; p++){
            const int r = rr + p * 32;
            cp16(sA + SW128(r * 128 + vv * 16),
                 g_X + (size_t)(i0 + r) * DIM + kc + vv * 8);
            cp16(sB + SW128(r * 128 + vv * 16),
                 g_X + (size_t)(j0 + r) * DIM + kc + vv * 8);
        }
    };

    load_stage(0); CP_COMMIT();
    load_stage(1); CP_COMMIT();

    const int wm0 = (wid & 3) * 32;     // 4 warps in M
    const int wn0 = (wid >> 2) * 64;    // 2 warps in N

    float acc[2][8][4];                 // warp tile 32x64
    #pragma unroll
    for (int tm = 0; tm < 2; tm++)
        #pragma unroll
        for (int tn = 0; tn < 8; tn++)
            #pragma unroll
            for (int e = 0; e < 4; e++) acc[tm][tn][e] = 0.f;

    const int lrow = lane & 15, lhi = lane >> 4;

    for (int c = 0; c < NCHUNK; c++){
        CP_WAIT(1);
        __syncthreads();                 // single barrier per chunk (3-stage proof)
        if (c + 2 < NCHUNK) load_stage(c + 2);
        CP_COMMIT();                     // empty commits keep wait_group(1) aligned

        const uint32_t sA = sb + 1024 + (c % STAGES) * STAGE_BYTES;
        const uint32_t sB = sA + 16384;
        #pragma unroll
        for (int ks = 0; ks < 4; ks++){
            const int cb = ks * 32 + lhi * 16;
            uint32_t a[2][4];
            #pragma unroll
            for (int tm = 0; tm < 2; tm++)
                ldm_x4(a[tm], sA + SW128((wm0 + tm * 16 + lrow) * 128 + cb));
            uint32_t b[4][4];
            #pragma unroll
            for (int tp = 0; tp < 4; tp++)
                ldm_x4(b[tp], sB + SW128((wn0 + tp * 16 + lrow) * 128 + cb));
            #pragma unroll
            for (int tm = 0; tm < 2; tm++)
                #pragma unroll
                for (int tp = 0; tp < 4; tp++){
                    mma16816(acc[tm][2*tp],     a[tm], b[tp][0], b[tp][2]);
                    mma16816(acc[tm][2*tp + 1], a[tm], b[tp][1], b[tp][3]);
                }
        }
    }

    // ---------------- fused masked loss on register accumulators ----------------
    const int r0 = lane >> 2, c0 = (lane & 3) * 2;
    float loss = 0.f;
    #pragma unroll
    for (int tm = 0; tm < 2; tm++){
        const int rowA = wm0 + tm * 16 + r0;
        const int liA  = ilab[rowA];
        const int liB  = ilab[rowA + 8];
        #pragma unroll
        for (int tn = 0; tn < 8; tn++){
            const int colb = wn0 + tn * 8 + c0;
            const int lj0 = jlab[colb], lj1 = jlab[colb + 1];
            #pragma unroll
            for (int e = 0; e < 4; e++){
                const float v = acc[tm][tn][e];
                const int row = (e >> 1) ? rowA + 8 : rowA;
                const int li  = (e >> 1) ? liB : liA;
                const int lj  = (e & 1) ? lj1 : lj0;
                float w = 2.f;
                if (diag){
                    const int gi = row, gj = colb + (e & 1);
                    w = (gi < gj) ? 2.f : ((gi == gj) ? 1.f : 0.f);
                }
                float l;
                if (li == lj) l = (v < 1.f) ? (1.f - v) : 0.f;
                else          l = (v > MARGINF) ? v : 0.f;
                loss += w * l;
            }
        }
    }

    // block reduction -> per-tile partial.
    // wsum lives in the stage-0 smem region: all stage-0 reads (last use: chunk 6)
    // are ordered before the top-of-chunk-7 barrier, so no extra barrier is needed
    // between the loss loop (reads labels @smem+0..1023) and this store.
    #pragma unroll
    for (int o = 16; o; o >>= 1) loss += __shfl_xor_sync(0xffffffffu, loss, o);
    float* wsum = (float*)(smem + 1024);
    if (lane == 0) wsum[wid] = loss;
    __syncthreads();
    if (tid == 0){
        float s = 0.f;
        #pragma unroll
        for (int w = 0; w < 8; w++) s += wsum[w];
        g_part[blockIdx.x] = s;
    }
}

// ---------------- kernel 3: deterministic final reduction ----------------
__global__ void reduce_kernel(float* __restrict__ out){
    __shared__ float sm[256];
    const int t = threadIdx.x;
    // 9 independent loads (MLP), fixed order
    float v[9];
    #pragma unroll
    for (int k = 0; k < 9; k++){
        const int i = t + k * 256;
        v[k] = (i < NPART) ? g_part[i] : 0.f;
    }
    sm[t] = ((v[0] + v[1]) + (v[2] + v[3])) + ((v[4] + v[5]) + (v[6] + v[7])) + v[8];
    __syncthreads();
    for (int s = 128; s > 0; s >>= 1){
        if (t < s) sm[t] += sm[t + s];
        __syncthreads();
    }
    if (t == 0) out[0] = sm[0] / (float)NPTS;
}

// ---------------- launch ----------------
extern "C" void kernel_launch(void* const* d_in, const int* in_sizes, int n_in,
                              void* d_out, int out_size){
    const float* x   = (const float*)d_in[0];
    const void*  tgt = d_in[1];
    float* out = (float*)d_out;

    cudaFuncSetAttribute(contrastive_gemm,
                         cudaFuncAttributeMaxDynamicSharedMemorySize, SMEM_BYTES);

    prep_kernel<<<NPTS*DIM/1024, 256>>>(x, tgt);
    contrastive_gemm<<<NPART, 256, SMEM_BYTES>>>();
    reduce_kernel<<<1, 256>>>(out);
}